// round 10
// baseline (speedup 1.0000x reference)
#include <cuda_runtime.h>
#include <math.h>
#include <float.h>

#define Bn 128
#define Tn 64
#define Cn 6625
#define Ln 25
#define Kn 6
#define NEGF (-1e30f)
#define ALPHA_C 0.1f
#define TAIL_C 0.01f
#define NSEQ (Bn + Bn*Kn)      // 896
#define NCAND 128
#define NLAB 176               // 25 master + 150 smooth + 1 blank (slot 175)
#define FULLM 0xffffffffu
#define VRPT 7                 // 7*256*4 = 7168 >= 6625
#define CTCB (NSEQ/4)          // 224 ctc blocks
#define BCB (Bn + CTCB)        // 352 blocks in k_bc2

// ---------------- device scratch ----------------
__device__ float g_logZ[Bn*Tn];
__device__ float g_m1[Bn*Tn];
__device__ float g_m2[Bn*Tn];
__device__ int   g_i1[Bn*Tn];
__device__ int   g_i2[Bn*Tn];
__device__ float g_lpb0[Bn*Tn];
__device__ float g_tbl[Bn*Tn*NCAND];    // 4MB beam candidate RAW logit table
__device__ float g_lab[Bn*Tn*NLAB];     // 5.8MB label-slot lp table (L2 resident)
__device__ float g_conf[Bn];
__device__ float g_nll[NSEQ];
__device__ unsigned int g_ctr;

__device__ __forceinline__ float lae(float a, float b) {
    float mx = fmaxf(a, b), mn = fminf(a, b);
    return mx + __logf(1.f + __expf(mn - mx));
}
__device__ __forceinline__ float lae3(float a, float b, float c) {
    float m = fmaxf(a, fmaxf(b, c));
    return m + __logf(__expf(a - m) + __expf(b - m) + __expf(c - m));
}
__device__ __forceinline__ unsigned int fkey(float v) {
    unsigned int b = __float_as_uint(v);
    return (b & 0x80000000u) ? ~b : (b | 0x80000000u);
}

// owner-thread rescan (tid-strided layout; L1/L2-hot reload)
__device__ __noinline__ int rescan_idx(const float* __restrict__ p,
        int tid, int a0, int nv, int rem, float target, int excl) {
    const float4* pv = (const float4*)(p + a0);
    int best = 0x7fffffff;
    if (tid >= 1 && tid < a0 && __ldg(p + tid) == target && tid != excl) best = tid;
    for (int k = 0; k < VRPT; k++) {
        int idx = tid + k * 256;
        if (idx < nv) {
            float4 v = __ldg(pv + idx);
            int cb = a0 + (idx << 2);
            if (cb >= 1 && cb != excl && v.x == target && cb < best) best = cb;
            if (cb+1 != excl && v.y == target && cb+1 < best) best = cb+1;
            if (cb+2 != excl && v.z == target && cb+2 < best) best = cb+2;
            if (cb+3 != excl && v.w == target && cb+3 < best) best = cb+3;
        }
    }
    int ct = a0 + (nv << 2) + tid;
    if (tid < rem && __ldg(p + ct) == target && ct != excl && ct < best) best = ct;
    return best;
}
__device__ __noinline__ float rescan_max_excl(const float* __restrict__ p,
        int tid, int a0, int nv, int rem, int excl) {
    const float4* pv = (const float4*)(p + a0);
    float m = -FLT_MAX;
    if (tid >= 1 && tid < a0 && tid != excl) m = fmaxf(m, __ldg(p + tid));
    for (int k = 0; k < VRPT; k++) {
        int idx = tid + k * 256;
        if (idx < nv) {
            float4 v = __ldg(pv + idx);
            int cb = a0 + (idx << 2);
            if (cb >= 1 && cb != excl) m = fmaxf(m, v.x);
            if (cb+1 != excl) m = fmaxf(m, v.y);
            if (cb+2 != excl) m = fmaxf(m, v.z);
            if (cb+3 != excl) m = fmaxf(m, v.w);
        }
    }
    int ct = a0 + (nv << 2) + tid;
    if (tid < rem && ct != excl) m = fmaxf(m, __ldg(p + ct));
    return m;
}

// ---- kernel 1: block-per-row stats + fused label & transposed candidate gather ----
__global__ __launch_bounds__(256) void k_rowstats(
    const float* __restrict__ preds,
    const int* __restrict__ text,
    const int* __restrict__ smooth_text)
{
    int row = blockIdx.x;
    const float* p = preds + (long long)row * Cn;
    int tid = threadIdx.x;
    int lane = tid & 31, wid = tid >> 5;

    if (row == 0 && tid == 0) g_ctr = 0u;

    int a0 = (4 - ((row * Cn) & 3)) & 3;
    int nv = (Cn - a0) >> 2;
    int rem = Cn - a0 - (nv << 2);
    const float4* pv = (const float4*)(p + a0);

    float sum0 = 0.f, sum1 = 0.f;
    float cmx = -FLT_MAX;

    {
        float pe = (tid < a0) ? __ldg(p + tid) : NEGF;
        sum0 += __expf(pe);
        if (tid >= 1) cmx = fmaxf(cmx, pe);
    }
    {
        int ct = a0 + (nv << 2) + tid;
        float tv = (tid < rem) ? __ldg(p + ct) : NEGF;
        sum1 += __expf(tv);
        cmx = fmaxf(cmx, tv);
    }
#pragma unroll
    for (int k = 0; k < VRPT; k++) {
        int idx = tid + k * 256;
        bool ok = (idx < nv);
        float4 v = ok ? __ldg(pv + idx) : make_float4(NEGF, NEGF, NEGF, NEGF);
        sum0 += __expf(v.x) + __expf(v.y);
        sum1 += __expf(v.z) + __expf(v.w);
        float vx = (a0 == 0 && idx == 0) ? NEGF : v.x;
        cmx = fmaxf(fmaxf(cmx, fmaxf(vx, v.y)), fmaxf(v.z, v.w));
    }
    float sum = sum0 + sum1;

    unsigned long long key = ((unsigned long long)fkey(cmx) << 32) | (unsigned)tid;
#pragma unroll
    for (int off = 16; off > 0; off >>= 1) {
        sum += __shfl_xor_sync(FULLM, sum, off);
        unsigned long long o = __shfl_xor_sync(FULLM, key, off);
        key = (o > key) ? o : key;
    }
    __shared__ float s_s[8];
    __shared__ unsigned long long s_k[8];
    __shared__ float s_m1, s_m2, s_loc2, s_lz;
    __shared__ int s_i1, s_i2;
    __shared__ unsigned long long s_key;
    if (lane == 0) { s_s[wid] = sum; s_k[wid] = key; }
    __syncthreads();
    if (wid == 0) {
        float sm = (lane < 8) ? s_s[lane] : 0.f;
        unsigned long long u = (lane < 8) ? s_k[lane] : 0ull;
#pragma unroll
        for (int off = 4; off > 0; off >>= 1) {
            sm += __shfl_xor_sync(FULLM, sm, off);
            unsigned long long o = __shfl_xor_sync(FULLM, u, off);
            u = (o > u) ? o : u;
        }
        if (lane == 0) { s_lz = __logf(sm); s_key = u; }
    }
    __syncthreads();

    int T1 = (int)(s_key & 0xFFFFFFFFull);
    if (tid == T1) {
        s_m1 = cmx;
        int i1 = rescan_idx(p, tid, a0, nv, rem, cmx, -1);
        s_i1 = i1;
        s_loc2 = rescan_max_excl(p, tid, a0, nv, rem, i1);
    }
    __syncthreads();

    float val2 = (tid == T1) ? s_loc2 : cmx;
    unsigned long long key2 = ((unsigned long long)fkey(val2) << 32) | (unsigned)tid;
#pragma unroll
    for (int off = 16; off > 0; off >>= 1) {
        unsigned long long o = __shfl_xor_sync(FULLM, key2, off);
        key2 = (o > key2) ? o : key2;
    }
    if (lane == 0) s_k[wid] = key2;
    __syncthreads();
    if (wid == 0) {
        unsigned long long u = (lane < 8) ? s_k[lane] : 0ull;
#pragma unroll
        for (int off = 4; off > 0; off >>= 1) {
            unsigned long long o = __shfl_xor_sync(FULLM, u, off);
            u = (o > u) ? o : u;
        }
        if (lane == 0) s_key = u;
    }
    __syncthreads();
    int T2 = (int)(s_key & 0xFFFFFFFFull);
    if (tid == T2) {
        float m2 = (tid == T1) ? s_loc2 : cmx;
        s_m2 = m2;
        s_i2 = rescan_idx(p, tid, a0, nv, rem, m2, s_i1);
    }
    __syncthreads();

    float lz = s_lz;
    if (tid == 0) {
        g_logZ[row] = lz;
        g_m1[row] = s_m1;  g_i1[row] = s_i1;
        g_m2[row] = s_m2;  g_i2[row] = s_i2;
        g_lpb0[row] = __ldg(p) - lz;
    }

    int b = row >> 6;
    int t = row & 63;

    if (tid < NLAB) {
        int ch;
        if (tid < Ln)            ch = __ldg(text + b * Ln + tid);
        else if (tid < NLAB - 1) ch = __ldg(smooth_text + b * (Kn * Ln) + (tid - Ln));
        else                     ch = 0;
        g_lab[(long long)row * NLAB + tid] = __ldg(p + ch) - lz;
    }

    if (tid < 2 * Tn) {
        int tp = tid & 63;
        int ch = (tid < Tn) ? s_i1 : s_i2;
        int j  = (tid < Tn) ? t : (Tn + t);
        g_tbl[(long long)(b * Tn + tp) * NCAND + j] =
            __ldg(preds + (long long)(b * Tn + tp) * Cn + ch);
    }
}

// ---------------- kernel 2: beam blocks + ctc warps + final ----------------
__global__ __launch_bounds__(128) void k_bc2(
    const int* __restrict__ text,
    const int* __restrict__ preds_size,
    const int* __restrict__ length,
    const int* __restrict__ smooth_text,
    const int* __restrict__ smooth_length,
    float* __restrict__ out)
{
    int tid = threadIdx.x;
    __shared__ float stbl[Tn * NCAND];
    __shared__ float spm1[Tn], spm2[Tn], slpb[Tn], slz[Tn];
    __shared__ int   si1[Tn], si2[Tn];
    __shared__ unsigned int s_old;
    __shared__ float red[NCAND];

    if (blockIdx.x < Bn) {
        int b = blockIdx.x;
        if (tid < Tn) {
            int r = b * Tn + tid;
            float lzv = g_logZ[r];
            slz[tid]  = lzv;
            spm1[tid] = g_m1[r] - lzv;            // precomputed lp of top-1
            spm2[tid] = g_m2[r] - lzv;            // precomputed lp of top-2
            si1[tid] = g_i1[r]; si2[tid] = g_i2[r];
            slpb[tid] = g_lpb0[r];
        }
        __syncthreads();
        const float* gt = g_tbl + (long long)b * Tn * NCAND;
#pragma unroll 8
        for (int idx = tid; idx < Tn * NCAND; idx += 128)
            stbl[idx] = gt[idx] - slz[idx >> 7];
        __syncthreads();

        if (tid == 0) {
            // state: tot == lae(lpb, lpnb) carried exactly
            float tot = 0.f;                      // lae(0, NEGF) == 0
            float lpb = 0.f, lpnb = NEGF;
            int last = -1, lastj = 0;
            for (int t = 0; t < Tn; t++) {
                float lp_last = (last >= 0) ? stbl[t * NCAND + lastj] : NEGF;
                float new_pb = tot + slpb[t];
                float rep    = (last >= 0) ? (lpnb + lp_last) : NEGF;
                float keep   = lae(new_pb, rep);

                bool same = (si1[t] == last);
                float cA = (same ? lpb : tot) + spm1[t];
                float cB = tot + spm2[t];
                bool pickA = !same || (cA > cB) || (cA == cB && last < si2[t]);
                float best_ext = pickA ? cA : cB;
                int best_c = pickA ? si1[t] : si2[t];
                int best_j = pickA ? t : (Tn + t);

                bool take = best_ext > keep;
                lpb   = take ? NEGF     : new_pb;
                lpnb  = take ? best_ext : rep;
                tot   = take ? best_ext : keep;   // == lae(lpb, lpnb), exactly
                last  = take ? best_c   : last;
                lastj = take ? best_j   : lastj;
            }
            g_conf[b] = __expf(tot / (float)Tn);  // tot == lae(lpb, lpnb)
        }
    } else {
        int warp = tid >> 5, l = tid & 31;
        int n = (blockIdx.x - Bn) * 4 + warp;

        int b, tlen, ilen, sb;
        const int* lab;
        if (n < Bn) {
            b = n; sb = 0; lab = text + n * Ln;
            tlen = __ldg(length + n); ilen = __ldg(preds_size + n);
        } else {
            int m = n - Bn;
            b = m / Kn;
            int k = m - b * Kn;
            sb = Ln + k * Ln;
            lab = smooth_text + m * Ln;
            tlen = __ldg(smooth_length + m); ilen = Tn;
        }

        int lab_l = (l < Ln) ? __ldg(lab + l) : 0;
        int lab_p = __shfl_up_sync(FULLM, lab_l, 1);
        bool skip1 = (l >= 1) && (l < Ln) && (lab_l != lab_p);
        bool v0 = (l <= 25), v1 = (l <= 24);
        bool ldok = (l < Ln);

        const float* labp = g_lab + (long long)(b * Tn) * NLAB + sb + l;
        const float* blkp = g_lab + (long long)(b * Tn) * NLAB + (NLAB - 1);

        float c0  = ldok ? __ldg(labp) : NEGF;
        float bl0 = __ldg(blkp);
        float a0 = (l == 0) ? bl0 : NEGF;
        float a1 = (l == 0) ? c0  : NEGF;

        float pf[8], pblk[8];
#pragma unroll
        for (int q = 0; q < 8; q++) {
            pf[q]   = ldok ? __ldg(labp + (1 + q) * NLAB) : 0.f;
            pblk[q] = __ldg(blkp + (1 + q) * NLAB);
        }

#pragma unroll 4
        for (int t = 1; t < Tn; t++) {
            float raw  = pf[(t - 1) & 7];
            float lpbt = pblk[(t - 1) & 7];
            if (t + 8 < Tn) {
                if (ldok) pf[(t - 1) & 7] = __ldg(labp + (t + 8) * NLAB);
                pblk[(t - 1) & 7] = __ldg(blkp + (t + 8) * NLAB);
            }
            float p1 = __shfl_up_sync(FULLM, a1, 1);
            if (l == 0) p1 = NEGF;

            float tot0 = lae(a0, p1);
            float tot1 = lae3(a1, a0, skip1 ? p1 : NEGF);
            float n0 = tot0 + lpbt;
            float n1 = tot1 + raw;
            bool act = (t < ilen);
            a0 = act ? (v0 ? n0 : NEGF) : a0;
            a1 = act ? (v1 ? n1 : NEGF) : a1;
        }

        float ab = __shfl_sync(FULLM, a0, tlen);
        float ac = __shfl_sync(FULLM, a1, tlen - 1);
        if (l == 0) {
            float nll = -lae(ab, ac);
            if (nll > 1e29f) nll = 0.f;
            g_nll[n] = nll;
        }
    }

    // -------- last-block final reduction --------
    __syncthreads();
    __threadfence();
    if (tid == 0) s_old = atomicAdd(&g_ctr, 1u);
    __syncthreads();
    if (s_old == (unsigned)(BCB - 1)) {
        volatile float* vnll  = g_nll;
        volatile float* vconf = g_conf;
        int bb = tid;
        float lm = vnll[bb] / (float)__ldg(length + bb);
        float lc = 0.f;
#pragma unroll
        for (int k = 0; k < Kn; k++)
            lc += vnll[Bn + bb * Kn + k] / (float)__ldg(smooth_length + bb * Kn + k);
        lc *= (1.f / (float)Kn);
        float conf = vconf[bb];
        float omc = 1.f - conf;
        float r = TAIL_C + (1.f - TAIL_C) * omc * omc;
        red[bb] = lm + ALPHA_C * r * lc;
        __syncthreads();
        for (int off = Bn / 2; off > 0; off >>= 1) {
            if (bb < off) red[bb] += red[bb + off];
            __syncthreads();
        }
        if (bb == 0) out[0] = red[0] / (float)Bn;
    }
}

// ---------------- launch ----------------
extern "C" void kernel_launch(void* const* d_in, const int* in_sizes, int n_in,
                              void* d_out, int out_size) {
    const float* preds         = (const float*)d_in[0];
    const int*   text          = (const int*)d_in[1];
    const int*   preds_size    = (const int*)d_in[2];
    const int*   length        = (const int*)d_in[3];
    const int*   smooth_text   = (const int*)d_in[4];
    const int*   smooth_length = (const int*)d_in[5];
    float* out = (float*)d_out;

    k_rowstats<<<Bn * Tn, 256>>>(preds, text, smooth_text);
    k_bc2     <<<BCB, 128>>>(text, preds_size, length,
                             smooth_text, smooth_length, out);
}

// round 11
// speedup vs baseline: 1.2555x; 1.2555x over previous
#include <cuda_runtime.h>
#include <math.h>
#include <float.h>

#define Bn 128
#define Tn 64
#define Cn 6625
#define Ln 25
#define Kn 6
#define NEGF (-1e30f)
#define ALPHA_C 0.1f
#define TAIL_C 0.01f
#define NSEQ (Bn + Bn*Kn)      // 896
#define NCAND 128
#define NLAB 176               // 25 master + 150 smooth + 1 blank (slot 175)
#define FULLM 0xffffffffu
#define VRPT 7                 // 7*256*4 = 7168 >= 6625
#define CTCB (NSEQ/4)          // 224 ctc blocks
#define BCB (Bn + CTCB)        // 352 blocks in k_bc2

// ---------------- device scratch ----------------
__device__ float g_logZ[Bn*Tn];
__device__ float g_m1[Bn*Tn];
__device__ float g_m2[Bn*Tn];
__device__ int   g_i1[Bn*Tn];
__device__ int   g_i2[Bn*Tn];
__device__ float g_lpb0[Bn*Tn];
__device__ float g_tbl[Bn*Tn*NCAND];    // 4MB beam candidate RAW logit table
__device__ float g_lab[Bn*Tn*NLAB];     // 5.8MB label-slot lp table (L2 resident)
__device__ float g_conf[Bn];
__device__ float g_nll[NSEQ];
__device__ unsigned int g_ctr;

__device__ __forceinline__ float lae(float a, float b) {
    float mx = fmaxf(a, b), mn = fminf(a, b);
    return mx + __logf(1.f + __expf(mn - mx));
}
__device__ __forceinline__ float lae3(float a, float b, float c) {
    float m = fmaxf(a, fmaxf(b, c));
    return m + __logf(__expf(a - m) + __expf(b - m) + __expf(c - m));
}
__device__ __forceinline__ unsigned int fkey(float v) {
    unsigned int b = __float_as_uint(v);
    return (b & 0x80000000u) ? ~b : (b | 0x80000000u);
}

// owner-thread rescan (tid-strided layout; L1/L2-hot reload)
__device__ __noinline__ int rescan_idx(const float* __restrict__ p,
        int tid, int a0, int nv, int rem, float target, int excl) {
    const float4* pv = (const float4*)(p + a0);
    int best = 0x7fffffff;
    if (tid >= 1 && tid < a0 && __ldg(p + tid) == target && tid != excl) best = tid;
    for (int k = 0; k < VRPT; k++) {
        int idx = tid + k * 256;
        if (idx < nv) {
            float4 v = __ldg(pv + idx);
            int cb = a0 + (idx << 2);
            if (cb >= 1 && cb != excl && v.x == target && cb < best) best = cb;
            if (cb+1 != excl && v.y == target && cb+1 < best) best = cb+1;
            if (cb+2 != excl && v.z == target && cb+2 < best) best = cb+2;
            if (cb+3 != excl && v.w == target && cb+3 < best) best = cb+3;
        }
    }
    int ct = a0 + (nv << 2) + tid;
    if (tid < rem && __ldg(p + ct) == target && ct != excl && ct < best) best = ct;
    return best;
}
__device__ __noinline__ float rescan_max_excl(const float* __restrict__ p,
        int tid, int a0, int nv, int rem, int excl) {
    const float4* pv = (const float4*)(p + a0);
    float m = -FLT_MAX;
    if (tid >= 1 && tid < a0 && tid != excl) m = fmaxf(m, __ldg(p + tid));
    for (int k = 0; k < VRPT; k++) {
        int idx = tid + k * 256;
        if (idx < nv) {
            float4 v = __ldg(pv + idx);
            int cb = a0 + (idx << 2);
            if (cb >= 1 && cb != excl) m = fmaxf(m, v.x);
            if (cb+1 != excl) m = fmaxf(m, v.y);
            if (cb+2 != excl) m = fmaxf(m, v.z);
            if (cb+3 != excl) m = fmaxf(m, v.w);
        }
    }
    int ct = a0 + (nv << 2) + tid;
    if (tid < rem && ct != excl) m = fmaxf(m, __ldg(p + ct));
    return m;
}

// ---- kernel 1: block-per-row stats + fused label & transposed candidate gather ----
__global__ __launch_bounds__(256) void k_rowstats(
    const float* __restrict__ preds,
    const int* __restrict__ text,
    const int* __restrict__ smooth_text)
{
    int row = blockIdx.x;
    const float* p = preds + (long long)row * Cn;
    int tid = threadIdx.x;
    int lane = tid & 31, wid = tid >> 5;

    if (row == 0 && tid == 0) g_ctr = 0u;

    int a0 = (4 - ((row * Cn) & 3)) & 3;
    int nv = (Cn - a0) >> 2;
    int rem = Cn - a0 - (nv << 2);
    const float4* pv = (const float4*)(p + a0);

    float sum0 = 0.f, sum1 = 0.f;
    float cmx = -FLT_MAX;

    {
        float pe = (tid < a0) ? __ldg(p + tid) : NEGF;
        sum0 += __expf(pe);
        if (tid >= 1) cmx = fmaxf(cmx, pe);
    }
    {
        int ct = a0 + (nv << 2) + tid;
        float tv = (tid < rem) ? __ldg(p + ct) : NEGF;
        sum1 += __expf(tv);
        cmx = fmaxf(cmx, tv);
    }
#pragma unroll
    for (int k = 0; k < VRPT; k++) {
        int idx = tid + k * 256;
        bool ok = (idx < nv);
        float4 v = ok ? __ldg(pv + idx) : make_float4(NEGF, NEGF, NEGF, NEGF);
        sum0 += __expf(v.x) + __expf(v.y);
        sum1 += __expf(v.z) + __expf(v.w);
        float vx = (a0 == 0 && idx == 0) ? NEGF : v.x;
        cmx = fmaxf(fmaxf(cmx, fmaxf(vx, v.y)), fmaxf(v.z, v.w));
    }
    float sum = sum0 + sum1;

    unsigned long long key = ((unsigned long long)fkey(cmx) << 32) | (unsigned)tid;
#pragma unroll
    for (int off = 16; off > 0; off >>= 1) {
        sum += __shfl_xor_sync(FULLM, sum, off);
        unsigned long long o = __shfl_xor_sync(FULLM, key, off);
        key = (o > key) ? o : key;
    }
    __shared__ float s_s[8];
    __shared__ unsigned long long s_k[8];
    __shared__ float s_m1, s_m2, s_loc2, s_lz;
    __shared__ int s_i1, s_i2;
    __shared__ unsigned long long s_key;
    if (lane == 0) { s_s[wid] = sum; s_k[wid] = key; }
    __syncthreads();
    if (wid == 0) {
        float sm = (lane < 8) ? s_s[lane] : 0.f;
        unsigned long long u = (lane < 8) ? s_k[lane] : 0ull;
#pragma unroll
        for (int off = 4; off > 0; off >>= 1) {
            sm += __shfl_xor_sync(FULLM, sm, off);
            unsigned long long o = __shfl_xor_sync(FULLM, u, off);
            u = (o > u) ? o : u;
        }
        if (lane == 0) { s_lz = __logf(sm); s_key = u; }
    }
    __syncthreads();

    int T1 = (int)(s_key & 0xFFFFFFFFull);
    if (tid == T1) {
        s_m1 = cmx;
        int i1 = rescan_idx(p, tid, a0, nv, rem, cmx, -1);
        s_i1 = i1;
        s_loc2 = rescan_max_excl(p, tid, a0, nv, rem, i1);
    }
    __syncthreads();

    float val2 = (tid == T1) ? s_loc2 : cmx;
    unsigned long long key2 = ((unsigned long long)fkey(val2) << 32) | (unsigned)tid;
#pragma unroll
    for (int off = 16; off > 0; off >>= 1) {
        unsigned long long o = __shfl_xor_sync(FULLM, key2, off);
        key2 = (o > key2) ? o : key2;
    }
    if (lane == 0) s_k[wid] = key2;
    __syncthreads();
    if (wid == 0) {
        unsigned long long u = (lane < 8) ? s_k[lane] : 0ull;
#pragma unroll
        for (int off = 4; off > 0; off >>= 1) {
            unsigned long long o = __shfl_xor_sync(FULLM, u, off);
            u = (o > u) ? o : u;
        }
        if (lane == 0) s_key = u;
    }
    __syncthreads();
    int T2 = (int)(s_key & 0xFFFFFFFFull);
    if (tid == T2) {
        float m2 = (tid == T1) ? s_loc2 : cmx;
        s_m2 = m2;
        s_i2 = rescan_idx(p, tid, a0, nv, rem, m2, s_i1);
    }
    __syncthreads();

    float lz = s_lz;
    if (tid == 0) {
        g_logZ[row] = lz;
        g_m1[row] = s_m1;  g_i1[row] = s_i1;
        g_m2[row] = s_m2;  g_i2[row] = s_i2;
        g_lpb0[row] = __ldg(p) - lz;
    }

    int b = row >> 6;
    int t = row & 63;

    if (tid < NLAB) {
        int ch;
        if (tid < Ln)            ch = __ldg(text + b * Ln + tid);
        else if (tid < NLAB - 1) ch = __ldg(smooth_text + b * (Kn * Ln) + (tid - Ln));
        else                     ch = 0;
        g_lab[(long long)row * NLAB + tid] = __ldg(p + ch) - lz;
    }

    if (tid < 2 * Tn) {
        int tp = tid & 63;
        int ch = (tid < Tn) ? s_i1 : s_i2;
        int j  = (tid < Tn) ? t : (Tn + t);
        g_tbl[(long long)(b * Tn + tp) * NCAND + j] =
            __ldg(preds + (long long)(b * Tn + tp) * Cn + ch);
    }
}

// ---------------- kernel 2: beam blocks + ctc warps + final ----------------
__global__ __launch_bounds__(128) void k_bc2(
    const int* __restrict__ text,
    const int* __restrict__ preds_size,
    const int* __restrict__ length,
    const int* __restrict__ smooth_text,
    const int* __restrict__ smooth_length,
    float* __restrict__ out)
{
    int tid = threadIdx.x;
    __shared__ float stbl[Tn * NCAND];
    __shared__ float spm1[Tn], spm2[Tn], slpb[Tn], slz[Tn];
    __shared__ int   si1[Tn], si2[Tn];
    __shared__ unsigned int s_old;
    __shared__ float red[NCAND];

    if (blockIdx.x < Bn) {
        int b = blockIdx.x;
        if (tid < Tn) {
            int r = b * Tn + tid;
            float lzv = g_logZ[r];
            slz[tid]  = lzv;
            spm1[tid] = g_m1[r] - lzv;
            spm2[tid] = g_m2[r] - lzv;
            si1[tid] = g_i1[r]; si2[tid] = g_i2[r];
            slpb[tid] = g_lpb0[r];
        }
        __syncthreads();
        const float* gt = g_tbl + (long long)b * Tn * NCAND;
#pragma unroll 8
        for (int idx = tid; idx < Tn * NCAND; idx += 128)
            stbl[idx] = gt[idx] - slz[idx >> 7];
        __syncthreads();

        if (tid == 0) {
            float tot = 0.f;                      // lae(0, NEGF) == 0
            float lpb = 0.f, lpnb = NEGF;
            int last = -1, lastj = 0;
            for (int t = 0; t < Tn; t++) {
                float lp_last = (last >= 0) ? stbl[t * NCAND + lastj] : NEGF;
                float new_pb = tot + slpb[t];
                float rep    = (last >= 0) ? (lpnb + lp_last) : NEGF;
                float keep   = lae(new_pb, rep);

                bool same = (si1[t] == last);
                float cA = (same ? lpb : tot) + spm1[t];
                float cB = tot + spm2[t];
                bool pickA = !same || (cA > cB) || (cA == cB && last < si2[t]);
                float best_ext = pickA ? cA : cB;
                int best_c = pickA ? si1[t] : si2[t];
                int best_j = pickA ? t : (Tn + t);

                bool take = best_ext > keep;
                lpb   = take ? NEGF     : new_pb;
                lpnb  = take ? best_ext : rep;
                tot   = take ? best_ext : keep;
                last  = take ? best_c   : last;
                lastj = take ? best_j   : lastj;
            }
            g_conf[b] = __expf(tot / (float)Tn);
        }
    } else {
        int warp = tid >> 5, l = tid & 31;
        int n = (blockIdx.x - Bn) * 4 + warp;

        int b, tlen, ilen, sb;
        const int* lab;
        if (n < Bn) {
            b = n; sb = 0; lab = text + n * Ln;
            tlen = __ldg(length + n); ilen = __ldg(preds_size + n);
        } else {
            int m = n - Bn;
            b = m / Kn;
            int k = m - b * Kn;
            sb = Ln + k * Ln;
            lab = smooth_text + m * Ln;
            tlen = __ldg(smooth_length + m); ilen = Tn;
        }

        int lab_l = (l < Ln) ? __ldg(lab + l) : 0;
        int lab_p = __shfl_up_sync(FULLM, lab_l, 1);
        bool skip1 = (l >= 1) && (l < Ln) && (lab_l != lab_p);
        bool v0 = (l <= 25), v1 = (l <= 24);
        bool ldok = (l < Ln);

        const float* labp = g_lab + (long long)(b * Tn) * NLAB + sb + l;
        const float* blkp = g_lab + (long long)(b * Tn) * NLAB + (NLAB - 1);

        float c0  = ldok ? __ldg(labp) : NEGF;
        float bl0 = __ldg(blkp);
        float a0 = (l == 0) ? bl0 : NEGF;
        float a1 = (l == 0) ? c0  : NEGF;

        float pf[8], pblk[8];
#pragma unroll
        for (int q = 0; q < 8; q++) {
            pf[q]   = ldok ? __ldg(labp + (1 + q) * NLAB) : 0.f;
            pblk[q] = __ldg(blkp + (1 + q) * NLAB);
        }

        // FULL unroll: trip count 63 is compile-time, so all pf[(t-1)&7] /
        // pblk[(t-1)&7] indices become constants -> ring stays in registers
        // (partial unroll demoted both arrays to local memory: LDL/STL on the
        // dependent chain every iteration).
#pragma unroll
        for (int t = 1; t < Tn; t++) {
            float raw  = pf[(t - 1) & 7];
            float lpbt = pblk[(t - 1) & 7];
            if (t + 8 < Tn) {
                if (ldok) pf[(t - 1) & 7] = __ldg(labp + (t + 8) * NLAB);
                pblk[(t - 1) & 7] = __ldg(blkp + (t + 8) * NLAB);
            }
            float p1 = __shfl_up_sync(FULLM, a1, 1);
            if (l == 0) p1 = NEGF;

            float tot0 = lae(a0, p1);
            float tot1 = lae3(a1, a0, skip1 ? p1 : NEGF);
            float n0 = tot0 + lpbt;
            float n1 = tot1 + raw;
            bool act = (t < ilen);
            a0 = act ? (v0 ? n0 : NEGF) : a0;
            a1 = act ? (v1 ? n1 : NEGF) : a1;
        }

        float ab = __shfl_sync(FULLM, a0, tlen);
        float ac = __shfl_sync(FULLM, a1, tlen - 1);
        if (l == 0) {
            float nll = -lae(ab, ac);
            if (nll > 1e29f) nll = 0.f;
            g_nll[n] = nll;
        }
    }

    // -------- last-block final reduction --------
    __syncthreads();
    __threadfence();
    if (tid == 0) s_old = atomicAdd(&g_ctr, 1u);
    __syncthreads();
    if (s_old == (unsigned)(BCB - 1)) {
        volatile float* vnll  = g_nll;
        volatile float* vconf = g_conf;
        int bb = tid;
        float lm = vnll[bb] / (float)__ldg(length + bb);
        float lc = 0.f;
#pragma unroll
        for (int k = 0; k < Kn; k++)
            lc += vnll[Bn + bb * Kn + k] / (float)__ldg(smooth_length + bb * Kn + k);
        lc *= (1.f / (float)Kn);
        float conf = vconf[bb];
        float omc = 1.f - conf;
        float r = TAIL_C + (1.f - TAIL_C) * omc * omc;
        red[bb] = lm + ALPHA_C * r * lc;
        __syncthreads();
        for (int off = Bn / 2; off > 0; off >>= 1) {
            if (bb < off) red[bb] += red[bb + off];
            __syncthreads();
        }
        if (bb == 0) out[0] = red[0] / (float)Bn;
    }
}

// ---------------- launch ----------------
extern "C" void kernel_launch(void* const* d_in, const int* in_sizes, int n_in,
                              void* d_out, int out_size) {
    const float* preds         = (const float*)d_in[0];
    const int*   text          = (const int*)d_in[1];
    const int*   preds_size    = (const int*)d_in[2];
    const int*   length        = (const int*)d_in[3];
    const int*   smooth_text   = (const int*)d_in[4];
    const int*   smooth_length = (const int*)d_in[5];
    float* out = (float*)d_out;

    k_rowstats<<<Bn * Tn, 256>>>(preds, text, smooth_text);
    k_bc2     <<<BCB, 128>>>(text, preds_size, length,
                             smooth_text, smooth_length, out);
}